// round 1
// baseline (speedup 1.0000x reference)
#include <cuda_runtime.h>
#include <math.h>

#define B_  32
#define L_  4096
#define D_  512
#define H_  8
#define DH_ 64
#define P_  16
#define NL_ 8
#define FF_ 2048
#define NC_ 4
#define S_  257
#define M_  (B_*S_)      // 8224
#define NPATCH_ 256

// ---------------- scratch (device globals; no allocation allowed) ----------
__device__ float g_x[M_*D_];
__device__ float g_q[M_*D_];
__device__ float g_k[M_*D_];
__device__ float g_v[M_*D_];
__device__ float g_attn[M_*D_];
__device__ float g_ff[M_*FF_];
__device__ float g_kv[B_*H_*DH_*DH_];
__device__ float g_ksum[B_*H_*DH_];
__device__ float g_len[B_];
__device__ float g_wc[P_*D_*D_];   // conv_w transposed to (K=p*D+i, O)

// ---------------- helpers ---------------------------------------------------
__device__ __forceinline__ float block_sum(float v, float* sh) {
    int lane = threadIdx.x & 31, w = threadIdx.x >> 5;
    int nw = blockDim.x >> 5;
    #pragma unroll
    for (int o = 16; o > 0; o >>= 1) v += __shfl_xor_sync(0xffffffffu, v, o);
    if (lane == 0) sh[w] = v;
    __syncthreads();
    float tot = 0.f;
    for (int i = 0; i < nw; i++) tot += sh[i];
    __syncthreads();
    return tot;
}

__device__ __forceinline__ float gelu_exact(float v) {
    return 0.5f * v * (1.0f + erff(v * 0.70710678118654752f));
}

// ---------------- generic SGEMM: C = A(MxK) @ B(KxN) [+bias][+res][gelu] ----
// BM=BN=128, BK=16, 256 threads, 8x8 microtile.
__global__ __launch_bounds__(256) void sgemm_kernel(
    const float* __restrict__ A, const float* __restrict__ Bm,
    const float* __restrict__ bias, const float* __restrict__ res,
    float* __restrict__ C, int M, int N, int K, int act)
{
    __shared__ float As[16][128];
    __shared__ float Bs[16][128];
    int tid = threadIdx.x;
    int m0 = blockIdx.y * 128;
    int n0 = blockIdx.x * 128;

    int arow = tid >> 2;            // 0..63
    int acol = (tid & 3) * 4;       // 0,4,8,12
    int br   = tid >> 5;            // 0..7
    int bc   = (tid & 31) * 4;      // 0..124
    int ty = tid >> 4, tx = tid & 15;

    float acc[8][8];
    #pragma unroll
    for (int i = 0; i < 8; i++)
        #pragma unroll
        for (int j = 0; j < 8; j++) acc[i][j] = 0.f;

    for (int k0 = 0; k0 < K; k0 += 16) {
        #pragma unroll
        for (int half = 0; half < 2; half++) {
            int r = arow + half * 64;
            int gm = m0 + r;
            float4 av = make_float4(0.f, 0.f, 0.f, 0.f);
            if (gm < M)
                av = *reinterpret_cast<const float4*>(A + (size_t)gm * K + k0 + acol);
            As[acol + 0][r] = av.x;
            As[acol + 1][r] = av.y;
            As[acol + 2][r] = av.z;
            As[acol + 3][r] = av.w;
        }
        #pragma unroll
        for (int half = 0; half < 2; half++) {
            int r = br + half * 8;
            float4 bv = *reinterpret_cast<const float4*>(Bm + (size_t)(k0 + r) * N + n0 + bc);
            *reinterpret_cast<float4*>(&Bs[r][bc]) = bv;
        }
        __syncthreads();
        #pragma unroll
        for (int kk = 0; kk < 16; kk++) {
            float a[8], b[8];
            *reinterpret_cast<float4*>(&a[0]) = *reinterpret_cast<float4*>(&As[kk][ty * 8]);
            *reinterpret_cast<float4*>(&a[4]) = *reinterpret_cast<float4*>(&As[kk][ty * 8 + 4]);
            *reinterpret_cast<float4*>(&b[0]) = *reinterpret_cast<float4*>(&Bs[kk][tx * 8]);
            *reinterpret_cast<float4*>(&b[4]) = *reinterpret_cast<float4*>(&Bs[kk][tx * 8 + 4]);
            #pragma unroll
            for (int i = 0; i < 8; i++)
                #pragma unroll
                for (int j = 0; j < 8; j++) acc[i][j] += a[i] * b[j];
        }
        __syncthreads();
    }

    #pragma unroll
    for (int i = 0; i < 8; i++) {
        int row = m0 + ty * 8 + i;
        if (row >= M) continue;
        #pragma unroll
        for (int j = 0; j < 8; j++) {
            int col = n0 + tx * 8 + j;
            float v = acc[i][j];
            if (bias) v += bias[col];
            if (res)  v += res[(size_t)row * N + col];
            if (act)  v = gelu_exact(v);
            C[(size_t)row * N + col] = v;
        }
    }
}

// ---------------- fused embed+patch-conv GEMM -------------------------------
// C[m=(b,n), o] = sum_{k=(p,i)} emb[inputs[b, n*16+p], i] * g_wc[k, o]
// writes x[b*S + n + 1, o] = C + conv_b[o] + pos[n+1, o]
__global__ __launch_bounds__(256) void convgemm_kernel(
    const int* __restrict__ inputs, const float* __restrict__ emb,
    const float* __restrict__ conv_b, const float* __restrict__ pos)
{
    __shared__ float As[16][128];
    __shared__ float Bs[16][128];
    const int K = P_ * D_;   // 8192
    const int N = D_;
    int tid = threadIdx.x;
    int m0 = blockIdx.y * 128;
    int n0 = blockIdx.x * 128;

    int arow = tid >> 2;
    int acol = (tid & 3) * 4;
    int br   = tid >> 5;
    int bc   = (tid & 31) * 4;
    int ty = tid >> 4, tx = tid & 15;

    float acc[8][8];
    #pragma unroll
    for (int i = 0; i < 8; i++)
        #pragma unroll
        for (int j = 0; j < 8; j++) acc[i][j] = 0.f;

    for (int k0 = 0; k0 < K; k0 += 16) {
        #pragma unroll
        for (int half = 0; half < 2; half++) {
            int r = arow + half * 64;
            int gm = m0 + r;                       // < 8192 always
            int bb = gm >> 8, nn = gm & 255;
            int k = k0 + acol;
            int p = k >> 9, ii = k & 511;
            int token = inputs[(bb << 12) + (nn << 4) + p];
            float4 av = *reinterpret_cast<const float4*>(emb + (size_t)token * D_ + ii);
            As[acol + 0][r] = av.x;
            As[acol + 1][r] = av.y;
            As[acol + 2][r] = av.z;
            As[acol + 3][r] = av.w;
        }
        #pragma unroll
        for (int half = 0; half < 2; half++) {
            int r = br + half * 8;
            float4 bv = *reinterpret_cast<const float4*>(g_wc + (size_t)(k0 + r) * N + n0 + bc);
            *reinterpret_cast<float4*>(&Bs[r][bc]) = bv;
        }
        __syncthreads();
        #pragma unroll
        for (int kk = 0; kk < 16; kk++) {
            float a[8], b[8];
            *reinterpret_cast<float4*>(&a[0]) = *reinterpret_cast<float4*>(&As[kk][ty * 8]);
            *reinterpret_cast<float4*>(&a[4]) = *reinterpret_cast<float4*>(&As[kk][ty * 8 + 4]);
            *reinterpret_cast<float4*>(&b[0]) = *reinterpret_cast<float4*>(&Bs[kk][tx * 8]);
            *reinterpret_cast<float4*>(&b[4]) = *reinterpret_cast<float4*>(&Bs[kk][tx * 8 + 4]);
            #pragma unroll
            for (int i = 0; i < 8; i++)
                #pragma unroll
                for (int j = 0; j < 8; j++) acc[i][j] += a[i] * b[j];
        }
        __syncthreads();
    }

    #pragma unroll
    for (int i = 0; i < 8; i++) {
        int gm = m0 + ty * 8 + i;
        int bb = gm >> 8, nn = gm & 255;
        size_t outrow = (size_t)bb * S_ + nn + 1;
        #pragma unroll
        for (int j = 0; j < 8; j++) {
            int col = n0 + tx * 8 + j;
            float v = acc[i][j] + conv_b[col] + pos[(size_t)(nn + 1) * D_ + col];
            g_x[outrow * D_ + col] = v;
        }
    }
}

// ---------------- small kernels ---------------------------------------------
__global__ void transpose_convw_kernel(const float* __restrict__ cw) {
    int idx = blockIdx.x * 256 + threadIdx.x;
    if (idx >= P_ * D_ * D_) return;
    int o = idx & 511;
    int k = idx >> 9;
    int ii = k & 511;
    int p  = k >> 9;
    g_wc[idx] = cw[((size_t)o * D_ + ii) * P_ + p];
}

__global__ void cls_kernel(const float* __restrict__ cls, const float* __restrict__ pos) {
    int b = blockIdx.x, d = threadIdx.x;
    g_x[(size_t)b * S_ * D_ + d] = cls[d] + pos[d];
}

__global__ void len_kernel(const float* __restrict__ mask) {
    __shared__ float sh[8];
    int b = blockIdx.x;
    float s = 0.f;
    for (int i = threadIdx.x; i < L_; i += 256) s += mask[(size_t)b * L_ + i];
    s = block_sum(s, sh);
    if (threadIdx.x == 0) g_len[b] = ceilf((s + 1.0f) / (float)P_);
}

// RoPE + elu(+1) (+length mask for K) in place on g_q / g_k
__global__ void rope_elu_kernel() {
    int idx = blockIdx.x * 256 + threadIdx.x;
    if (idx >= M_ * H_ * 32) return;
    int t = idx & 31;
    int h = (idx >> 5) & 7;
    int m = idx >> 8;
    int b = m / S_;
    int s = m - b * S_;
    size_t base = (size_t)m * D_ + h * DH_;
    // inv_freq[t] = 10000^(-2t/64)  => exp(-t * ln(10000)/32)
    float inv = expf(-(float)t * 0.28782313662425575f);
    float f = (float)s * inv;
    float c = cosf(f), sn = sinf(f);

    float q1 = g_q[base + t], q2 = g_q[base + t + 32];
    float qa = q1 * c - q2 * sn;
    float qb = q2 * c + q1 * sn;
    g_q[base + t]      = qa > 0.f ? qa + 1.f : expf(qa);
    g_q[base + t + 32] = qb > 0.f ? qb + 1.f : expf(qb);

    float lm = ((float)s < g_len[b]) ? 1.f : 0.f;
    float k1 = g_k[base + t], k2 = g_k[base + t + 32];
    float ka = k1 * c - k2 * sn;
    float kb = k2 * c + k1 * sn;
    g_k[base + t]      = (ka > 0.f ? ka + 1.f : expf(ka)) * lm;
    g_k[base + t + 32] = (kb > 0.f ? kb + 1.f : expf(kb)) * lm;
}

// kv[b,h,d,m] = sum_s kf[b,s,h,d] * v[b,s,h,m]   (one block per (b,h))
__global__ __launch_bounds__(256) void kv_kernel() {
    __shared__ float kfs[16][64];
    __shared__ float vs[16][64];
    int bh = blockIdx.x;
    int b = bh >> 3, h = bh & 7;
    int tid = threadIdx.x;
    int ty = tid >> 4, tx = tid & 15;
    float acc[4][4];
    #pragma unroll
    for (int i = 0; i < 4; i++)
        #pragma unroll
        for (int j = 0; j < 4; j++) acc[i][j] = 0.f;

    for (int s0 = 0; s0 < S_; s0 += 16) {
        #pragma unroll
        for (int p = 0; p < 4; p++) {
            int e = tid + p * 256;
            int sl = e >> 6, d = e & 63;
            int s = s0 + sl;
            float kvv = 0.f, vv = 0.f;
            if (s < S_) {
                size_t off = ((size_t)(b * S_ + s)) * D_ + h * DH_ + d;
                kvv = g_k[off];
                vv  = g_v[off];
            }
            kfs[sl][d] = kvv;
            vs[sl][d]  = vv;
        }
        __syncthreads();
        #pragma unroll
        for (int kk = 0; kk < 16; kk++) {
            float a[4], bb[4];
            #pragma unroll
            for (int i = 0; i < 4; i++) { a[i] = kfs[kk][ty * 4 + i]; bb[i] = vs[kk][tx * 4 + i]; }
            #pragma unroll
            for (int i = 0; i < 4; i++)
                #pragma unroll
                for (int j = 0; j < 4; j++) acc[i][j] += a[i] * bb[j];
        }
        __syncthreads();
    }
    #pragma unroll
    for (int i = 0; i < 4; i++)
        #pragma unroll
        for (int j = 0; j < 4; j++)
            g_kv[((size_t)bh * 64 + ty * 4 + i) * 64 + tx * 4 + j] = acc[i][j];
}

__global__ void ksum_kernel() {
    int bh = blockIdx.x;
    int b = bh >> 3, h = bh & 7;
    int d = threadIdx.x;   // 64
    float acc = 0.f;
    for (int s = 0; s < S_; s++)
        acc += g_k[((size_t)(b * S_ + s)) * D_ + h * DH_ + d];
    g_ksum[(size_t)bh * 64 + d] = acc;
}

// attn[m, h*64+j] = z * sum_d qf[m,h,d] * kv[b,h,d,j]
__global__ __launch_bounds__(256) void attn_kernel() {
    __shared__ float qf[512];
    int m = blockIdx.x;
    int b = m / S_;
    int tid = threadIdx.x;
    qf[tid]       = g_q[(size_t)m * D_ + tid];
    qf[tid + 256] = g_q[(size_t)m * D_ + tid + 256];
    __syncthreads();
    int h = tid >> 5, lane = tid & 31;
    const float* ks  = g_ksum + (size_t)(b * 8 + h) * 64;
    const float* qh  = qf + h * 64;
    const float* kvp = g_kv + (size_t)(b * 8 + h) * 4096;
    float zd = 0.f;
    #pragma unroll
    for (int d = 0; d < 64; d++) zd += qh[d] * ks[d];
    float z = 1.f / (zd + 1e-6f);
    float a0 = 0.f, a1 = 0.f;
    #pragma unroll
    for (int d = 0; d < 64; d++) {
        float qv = qh[d];
        a0 += qv * kvp[d * 64 + lane];
        a1 += qv * kvp[d * 64 + lane + 32];
    }
    g_attn[(size_t)m * D_ + h * 64 + lane]      = a0 * z;
    g_attn[(size_t)m * D_ + h * 64 + lane + 32] = a1 * z;
}

__global__ __launch_bounds__(256) void ln_kernel(
    float* __restrict__ x, const float* __restrict__ sc, const float* __restrict__ bi)
{
    __shared__ float sh[8];
    int row = blockIdx.x;
    float* p = x + (size_t)row * D_;
    int tid = threadIdx.x;
    float v0 = p[tid], v1 = p[tid + 256];
    float mean = block_sum(v0 + v1, sh) * (1.f / 512.f);
    float d0 = v0 - mean, d1 = v1 - mean;
    float var = block_sum(d0 * d0 + d1 * d1, sh) * (1.f / 512.f);
    float rstd = rsqrtf(var + 1e-5f);
    p[tid]       = d0 * rstd * sc[tid] + bi[tid];
    p[tid + 256] = d1 * rstd * sc[tid + 256] + bi[tid + 256];
}

// final: LN(x[b,0]) @ out_w + out_b  -> out[b, 0..3]
__global__ __launch_bounds__(128) void final_kernel(
    const float* __restrict__ lnf_s, const float* __restrict__ lnf_b,
    const float* __restrict__ out_w, const float* __restrict__ out_b,
    float* __restrict__ out)
{
    __shared__ float sh[8];
    __shared__ float xn[512];
    int b = blockIdx.x;
    int tid = threadIdx.x;
    const float* p = g_x + (size_t)b * S_ * D_;
    float v[4];
    #pragma unroll
    for (int i = 0; i < 4; i++) v[i] = p[tid + i * 128];
    float mean = block_sum(v[0] + v[1] + v[2] + v[3], sh) * (1.f / 512.f);
    float sq = 0.f;
    #pragma unroll
    for (int i = 0; i < 4; i++) { float d = v[i] - mean; sq += d * d; }
    float var = block_sum(sq, sh) * (1.f / 512.f);
    float rstd = rsqrtf(var + 1e-5f);
    #pragma unroll
    for (int i = 0; i < 4; i++) {
        int d = tid + i * 128;
        xn[d] = (v[i] - mean) * rstd * lnf_s[d] + lnf_b[d];
    }
    __syncthreads();
    int w = tid >> 5, lane = tid & 31;
    float acc = 0.f;
    for (int d = lane; d < 512; d += 32) acc += xn[d] * out_w[d * NC_ + w];
    #pragma unroll
    for (int o = 16; o > 0; o >>= 1) acc += __shfl_xor_sync(0xffffffffu, acc, o);
    if (lane == 0) out[b * NC_ + w] = acc + out_b[w];
}

// ---------------- host driver -----------------------------------------------
extern "C" void kernel_launch(void* const* d_in, const int* in_sizes, int n_in,
                              void* d_out, int out_size)
{
    const int*   inputs = (const int*)  d_in[0];
    const float* mask   = (const float*)d_in[1];
    const float* emb    = (const float*)d_in[2];
    const float* conv_w = (const float*)d_in[3];
    const float* conv_b = (const float*)d_in[4];
    const float* pos    = (const float*)d_in[5];
    const float* cls    = (const float*)d_in[6];
    const float* Wq     = (const float*)d_in[7];
    const float* bq     = (const float*)d_in[8];
    const float* Wk     = (const float*)d_in[9];
    const float* bk     = (const float*)d_in[10];
    const float* Wv     = (const float*)d_in[11];
    const float* bv     = (const float*)d_in[12];
    const float* Wo     = (const float*)d_in[13];
    const float* bo     = (const float*)d_in[14];
    const float* ln1_s  = (const float*)d_in[15];
    const float* ln1_b  = (const float*)d_in[16];
    const float* ln2_s  = (const float*)d_in[17];
    const float* ln2_b  = (const float*)d_in[18];
    const float* W1     = (const float*)d_in[19];
    const float* b1     = (const float*)d_in[20];
    const float* W2     = (const float*)d_in[21];
    const float* b2     = (const float*)d_in[22];
    const float* lnf_s  = (const float*)d_in[23];
    const float* lnf_b  = (const float*)d_in[24];
    const float* out_w  = (const float*)d_in[25];
    const float* out_b  = (const float*)d_in[26];
    float* out = (float*)d_out;

    float *px, *pq, *pk, *pv, *pattn, *pff;
    cudaGetSymbolAddress((void**)&px,    g_x);
    cudaGetSymbolAddress((void**)&pq,    g_q);
    cudaGetSymbolAddress((void**)&pk,    g_k);
    cudaGetSymbolAddress((void**)&pv,    g_v);
    cudaGetSymbolAddress((void**)&pattn, g_attn);
    cudaGetSymbolAddress((void**)&pff,   g_ff);

    transpose_convw_kernel<<<(P_ * D_ * D_ + 255) / 256, 256>>>(conv_w);
    cls_kernel<<<B_, D_>>>(cls, pos);
    convgemm_kernel<<<dim3(D_ / 128, (B_ * NPATCH_) / 128), 256>>>(inputs, emb, conv_b, pos);
    len_kernel<<<B_, 256>>>(mask);

    dim3 gD(D_ / 128, (M_ + 127) / 128);    // (4, 65)
    dim3 gF(FF_ / 128, (M_ + 127) / 128);   // (16, 65)

    for (int i = 0; i < NL_; i++) {
        const float* wq = Wq + (size_t)i * D_ * D_;
        const float* wk = Wk + (size_t)i * D_ * D_;
        const float* wv = Wv + (size_t)i * D_ * D_;
        const float* wo = Wo + (size_t)i * D_ * D_;
        sgemm_kernel<<<gD, 256>>>(px, wq, bq + i * D_, nullptr, pq, M_, D_, D_, 0);
        sgemm_kernel<<<gD, 256>>>(px, wk, bk + i * D_, nullptr, pk, M_, D_, D_, 0);
        sgemm_kernel<<<gD, 256>>>(px, wv, bv + i * D_, nullptr, pv, M_, D_, D_, 0);
        rope_elu_kernel<<<(M_ * H_ * 32 + 255) / 256, 256>>>();
        kv_kernel<<<B_ * H_, 256>>>();
        ksum_kernel<<<B_ * H_, 64>>>();
        attn_kernel<<<M_, 256>>>();
        sgemm_kernel<<<gD, 256>>>(pattn, wo, bo + i * D_, px, px, M_, D_, D_, 0);
        ln_kernel<<<M_, 256>>>(px, ln1_s + i * D_, ln1_b + i * D_);
        sgemm_kernel<<<gF, 256>>>(px, W1 + (size_t)i * D_ * FF_, b1 + i * FF_, nullptr, pff, M_, FF_, D_, 1);
        sgemm_kernel<<<gD, 256>>>(pff, W2 + (size_t)i * FF_ * D_, b2 + i * D_, px, px, M_, D_, FF_, 0);
        ln_kernel<<<M_, 256>>>(px, ln2_s + i * D_, ln2_b + i * D_);
    }

    final_kernel<<<B_, 128>>>(lnf_s, lnf_b, out_w, out_b, out);
}

// round 3
// speedup vs baseline: 1.9773x; 1.9773x over previous
#include <cuda_runtime.h>
#include <cuda_bf16.h>
#include <cstdint>
#include <math.h>

#define B_  32
#define L_  4096
#define D_  512
#define H_  8
#define DH_ 64
#define P_  16
#define NL_ 8
#define FF_ 2048
#define NC_ 4
#define S_  257
#define M_  (B_*S_)      // 8224
#define MP_ 8320         // padded to 65*128
#define NPATCH_ 256

// ---------------- scratch (device globals; zero-initialized) ----------------
__device__ float g_x[M_*D_];
__device__ float g_q[M_*D_];
__device__ float g_k[M_*D_];
__device__ float g_v[M_*D_];
__device__ float g_kv[B_*H_*DH_*DH_];
__device__ float g_ksum[B_*H_*DH_];
__device__ float g_len[B_];

__device__ __nv_bfloat16 g_xhi[MP_*D_];
__device__ __nv_bfloat16 g_xlo[MP_*D_];
__device__ __nv_bfloat16 g_ahi[MP_*D_];
__device__ __nv_bfloat16 g_alo[MP_*D_];
__device__ __nv_bfloat16 g_fhi[MP_*FF_];
__device__ __nv_bfloat16 g_flo[MP_*FF_];

// transposed+split weights: conv [512][8192] then per-layer {q,k,v,o,w1,w2}
#define WOFF_CONV 0
#define WCNT_CONV (512*8192)
#define WOFF_L(i) (WCNT_CONV + (size_t)(i)*3145728)
#define WO_Q  0
#define WO_K  262144
#define WO_V  524288
#define WO_O  786432
#define WO_W1 1048576
#define WO_W2 2097152
#define WTOT (WCNT_CONV + (size_t)NL_*3145728)
__device__ __nv_bfloat16 g_whi[WTOT];
__device__ __nv_bfloat16 g_wlo[WTOT];

// ---------------- helpers ----------------------------------------------------
__device__ __forceinline__ uint32_t smem_u32(const void* p) {
    uint32_t a;
    asm("{ .reg .u64 t; cvta.to.shared.u64 t, %1; cvt.u32.u64 %0, t; }" : "=r"(a) : "l"(p));
    return a;
}
__device__ __forceinline__ void cp16(uint32_t dst, const void* src) {
    asm volatile("cp.async.cg.shared.global [%0], [%1], 16;" :: "r"(dst), "l"(src) : "memory");
}
#define CP_COMMIT() asm volatile("cp.async.commit_group;" ::: "memory")
#define CP_WAIT1()  asm volatile("cp.async.wait_group 1;" ::: "memory")
#define CP_WAIT0()  asm volatile("cp.async.wait_group 0;" ::: "memory")

__device__ __forceinline__ void mma_bf16(float* d, const uint32_t* a, const uint32_t* b) {
    asm volatile(
        "mma.sync.aligned.m16n8k16.row.col.f32.bf16.bf16.f32 "
        "{%0,%1,%2,%3}, {%4,%5,%6,%7}, {%8,%9}, {%0,%1,%2,%3};"
        : "+f"(d[0]), "+f"(d[1]), "+f"(d[2]), "+f"(d[3])
        : "r"(a[0]), "r"(a[1]), "r"(a[2]), "r"(a[3]), "r"(b[0]), "r"(b[1]));
}

__device__ __forceinline__ float gelu_exact(float v) {
    return 0.5f * v * (1.0f + erff(v * 0.70710678118654752f));
}
__device__ __forceinline__ void split_bf16(float v, __nv_bfloat16& h, __nv_bfloat16& l) {
    h = __float2bfloat16_rn(v);
    l = __float2bfloat16_rn(v - __bfloat162float(h));
}

// ---------------- HMMA GEMM --------------------------------------------------
// C(M,Ntot) = Ahi/lo(M,K) @ (Bhi/lo(Ntot,K))^T   [+bias][+res][gelu]
// CTA 128x256, 8 warps (2x4), warp 64x64, BK=32, 2-stage cp.async pipeline.
#define RS 20                 // words per smem row (32 halves + 8 pad = 80B)
#define ST_AHI 0
#define ST_ALO 10240
#define ST_BHI 20480
#define ST_BLO 40960
#define STAGE_BYTES 61440
#define SMEM_MMA (2*STAGE_BYTES)

__global__ __launch_bounds__(256, 1) void gemm_mma(
    const __nv_bfloat16* __restrict__ Ahi, const __nv_bfloat16* __restrict__ Alo,
    const __nv_bfloat16* __restrict__ Bhi, const __nv_bfloat16* __restrict__ Blo,
    const float* __restrict__ bias, const float* __restrict__ res,
    float* __restrict__ Cf, __nv_bfloat16* __restrict__ Chi, __nv_bfloat16* __restrict__ Clo,
    int M, int Ntot, int K, int act)
{
    extern __shared__ char sm[];
    uint32_t sbase = smem_u32(sm);
    int tid = threadIdx.x, wid = tid >> 5, lane = tid & 31;
    int g = lane >> 2, tig = lane & 3;
    int m0 = blockIdx.y * 128, n0 = blockIdx.x * 256;
    int warp_m = (wid >> 2) * 64, warp_n = (wid & 3) * 64;

    float acc[4][8][4];
    #pragma unroll
    for (int mt = 0; mt < 4; mt++)
        #pragma unroll
        for (int nt = 0; nt < 8; nt++)
            #pragma unroll
            for (int i = 0; i < 4; i++) acc[mt][nt][i] = 0.f;

    int S = K >> 5;

    auto issue = [&](int s) {
        int kb = s << 5;
        uint32_t stg = sbase + (uint32_t)(s & 1) * STAGE_BYTES;
        #pragma unroll
        for (int it = 0; it < 2; it++) {
            int item = tid + it * 256;
            int r = item >> 2, seg = item & 3;
            size_t goff = (size_t)(m0 + r) * K + kb + seg * 8;
            uint32_t d = stg + (uint32_t)(r * RS + seg * 4) * 4;
            cp16(d + ST_AHI, Ahi + goff);
            cp16(d + ST_ALO, Alo + goff);
        }
        #pragma unroll
        for (int it = 0; it < 4; it++) {
            int item = tid + it * 256;
            int r = item >> 2, seg = item & 3;
            size_t goff = (size_t)(n0 + r) * K + kb + seg * 8;
            uint32_t d = stg + (uint32_t)(r * RS + seg * 4) * 4;
            cp16(d + ST_BHI, Bhi + goff);
            cp16(d + ST_BLO, Blo + goff);
        }
        CP_COMMIT();
    };

    auto compute = [&](int s) {
        char* stp = sm + (size_t)(s & 1) * STAGE_BYTES;
        const uint32_t* Ahw = (const uint32_t*)(stp + ST_AHI);
        const uint32_t* Alw = (const uint32_t*)(stp + ST_ALO);
        const uint32_t* Bhw = (const uint32_t*)(stp + ST_BHI);
        const uint32_t* Blw = (const uint32_t*)(stp + ST_BLO);
        #pragma unroll
        for (int k16 = 0; k16 < 2; k16++) {
            int kw0 = k16 * 8;
            uint32_t ah[4][4], al[4][4];
            #pragma unroll
            for (int mt = 0; mt < 4; mt++) {
                int r0 = (warp_m + mt * 16 + g) * RS + kw0 + tig;
                int r1 = r0 + 8 * RS;
                ah[mt][0] = Ahw[r0];     ah[mt][1] = Ahw[r1];
                ah[mt][2] = Ahw[r0 + 4]; ah[mt][3] = Ahw[r1 + 4];
                al[mt][0] = Alw[r0];     al[mt][1] = Alw[r1];
                al[mt][2] = Alw[r0 + 4]; al[mt][3] = Alw[r1 + 4];
            }
            #pragma unroll
            for (int nt = 0; nt < 8; nt++) {
                int nb = (warp_n + nt * 8 + g) * RS + kw0 + tig;
                uint32_t bh[2] = { Bhw[nb], Bhw[nb + 4] };
                uint32_t bl[2] = { Blw[nb], Blw[nb + 4] };
                #pragma unroll
                for (int mt = 0; mt < 4; mt++) {
                    mma_bf16(acc[mt][nt], ah[mt], bh);
                    mma_bf16(acc[mt][nt], ah[mt], bl);
                    mma_bf16(acc[mt][nt], al[mt], bh);
                }
            }
        }
    };

    issue(0);
    for (int s = 0; s < S; s++) {
        if (s + 1 < S) { issue(s + 1); CP_WAIT1(); }
        else CP_WAIT0();
        __syncthreads();
        compute(s);
        __syncthreads();
    }

    // epilogue
    #pragma unroll
    for (int mt = 0; mt < 4; mt++) {
        #pragma unroll
        for (int i = 0; i < 2; i++) {
            int row = m0 + warp_m + mt * 16 + g + i * 8;
            if (row < M) {
                #pragma unroll
                for (int nt = 0; nt < 8; nt++) {
                    int col = n0 + warp_n + nt * 8 + tig * 2;
                    float v0 = acc[mt][nt][i * 2 + 0];
                    float v1 = acc[mt][nt][i * 2 + 1];
                    if (bias) { v0 += bias[col]; v1 += bias[col + 1]; }
                    if (res)  { v0 += res[(size_t)row * Ntot + col]; v1 += res[(size_t)row * Ntot + col + 1]; }
                    if (act)  { v0 = gelu_exact(v0); v1 = gelu_exact(v1); }
                    if (Cf)   { Cf[(size_t)row * Ntot + col] = v0; Cf[(size_t)row * Ntot + col + 1] = v1; }
                    if (Chi) {
                        __nv_bfloat16 h0, l0, h1, l1;
                        split_bf16(v0, h0, l0);
                        split_bf16(v1, h1, l1);
                        Chi[(size_t)row * Ntot + col] = h0; Chi[(size_t)row * Ntot + col + 1] = h1;
                        Clo[(size_t)row * Ntot + col] = l0; Clo[(size_t)row * Ntot + col + 1] = l1;
                    }
                }
            }
        }
    }
}

// ---------------- HMMA conv GEMM (embedding gather fused) --------------------
// A[m=(b,n)][k=(p,i)] = emb[inputs[b, n*16+p]][i], K=8192, N=512, M=8192.
__global__ __launch_bounds__(256, 1) void convgemm_mma(
    const int* __restrict__ inputs, const float* __restrict__ emb,
    const float* __restrict__ conv_b, const float* __restrict__ pos)
{
    extern __shared__ char sm[];
    uint32_t sbase = smem_u32(sm);
    const int K = P_ * D_;   // 8192
    int tid = threadIdx.x, wid = tid >> 5, lane = tid & 31;
    int g = lane >> 2, tig = lane & 3;
    int m0 = blockIdx.y * 128, n0 = blockIdx.x * 256;
    int warp_m = (wid >> 2) * 64, warp_n = (wid & 3) * 64;

    const __nv_bfloat16* Bhi = g_whi + WOFF_CONV;
    const __nv_bfloat16* Blo = g_wlo + WOFF_CONV;

    float acc[4][8][4];
    #pragma unroll
    for (int mt = 0; mt < 4; mt++)
        #pragma unroll
        for (int nt = 0; nt < 8; nt++)
            #pragma unroll
            for (int i = 0; i < 4; i++) acc[mt][nt][i] = 0.f;

    int S = K >> 5;   // 256

    auto issueB = [&](int s) {
        int kb = s << 5;
        uint32_t stg = sbase + (uint32_t)(s & 1) * STAGE_BYTES;
        #pragma unroll
        for (int it = 0; it < 4; it++) {
            int item = tid + it * 256;
            int r = item >> 2, seg = item & 3;
            size_t goff = (size_t)(n0 + r) * K + kb + seg * 8;
            uint32_t d = stg + (uint32_t)(r * RS + seg * 4) * 4;
            cp16(d + ST_BHI, Bhi + goff);
            cp16(d + ST_BLO, Blo + goff);
        }
        CP_COMMIT();
    };

    auto gatherA = [&](int s) {
        int kb = s << 5;
        int p = kb >> 9, i0 = kb & 511;
        char* stp = sm + (size_t)(s & 1) * STAGE_BYTES;
        #pragma unroll
        for (int it = 0; it < 2; it++) {
            int item = tid + it * 256;
            int r = item >> 2, seg = item & 3;
            int gm = m0 + r;
            int bb = gm >> 8, nn = gm & 255;
            int token = inputs[(bb << 12) + (nn << 4) + p];
            const float* src = emb + (size_t)token * D_ + i0 + seg * 8;
            float4 f0 = *(const float4*)(src);
            float4 f1 = *(const float4*)(src + 4);
            __nv_bfloat16 hh[8], ll[8];
            split_bf16(f0.x, hh[0], ll[0]); split_bf16(f0.y, hh[1], ll[1]);
            split_bf16(f0.z, hh[2], ll[2]); split_bf16(f0.w, hh[3], ll[3]);
            split_bf16(f1.x, hh[4], ll[4]); split_bf16(f1.y, hh[5], ll[5]);
            split_bf16(f1.z, hh[6], ll[6]); split_bf16(f1.w, hh[7], ll[7]);
            uint32_t woff = (uint32_t)(r * RS + seg * 4) * 4;
            *(uint4*)(stp + ST_AHI + woff) = *(uint4*)hh;
            *(uint4*)(stp + ST_ALO + woff) = *(uint4*)ll;
        }
    };

    auto compute = [&](int s) {
        char* stp = sm + (size_t)(s & 1) * STAGE_BYTES;
        const uint32_t* Ahw = (const uint32_t*)(stp + ST_AHI);
        const uint32_t* Alw = (const uint32_t*)(stp + ST_ALO);
        const uint32_t* Bhw = (const uint32_t*)(stp + ST_BHI);
        const uint32_t* Blw = (const uint32_t*)(stp + ST_BLO);
        #pragma unroll
        for (int k16 = 0; k16 < 2; k16++) {
            int kw0 = k16 * 8;
            uint32_t ah[4][4], al[4][4];
            #pragma unroll
            for (int mt = 0; mt < 4; mt++) {
                int r0 = (warp_m + mt * 16 + g) * RS + kw0 + tig;
                int r1 = r0 + 8 * RS;
                ah[mt][0] = Ahw[r0];     ah[mt][1] = Ahw[r1];
                ah[mt][2] = Ahw[r0 + 4]; ah[mt][3] = Ahw[r1 + 4];
                al[mt][0] = Alw[r0];     al[mt][1] = Alw[r1];
                al[mt][2] = Alw[r0 + 4]; al[mt][3] = Alw[r1 + 4];
            }
            #pragma unroll
            for (int nt = 0; nt < 8; nt++) {
                int nb = (warp_n + nt * 8 + g) * RS + kw0 + tig;
                uint32_t bh[2] = { Bhw[nb], Bhw[nb + 4] };
                uint32_t bl[2] = { Blw[nb], Blw[nb + 4] };
                #pragma unroll
                for (int mt = 0; mt < 4; mt++) {
                    mma_bf16(acc[mt][nt], ah[mt], bh);
                    mma_bf16(acc[mt][nt], ah[mt], bl);
                    mma_bf16(acc[mt][nt], al[mt], bh);
                }
            }
        }
    };

    issueB(0);
    gatherA(0);
    for (int s = 0; s < S; s++) {
        if (s + 1 < S) { issueB(s + 1); CP_WAIT1(); }
        else CP_WAIT0();
        __syncthreads();
        compute(s);
        if (s + 1 < S) gatherA(s + 1);
        __syncthreads();
    }

    #pragma unroll
    for (int mt = 0; mt < 4; mt++) {
        #pragma unroll
        for (int i = 0; i < 2; i++) {
            int row = m0 + warp_m + mt * 16 + g + i * 8;
            int bb = row >> 8, nn = row & 255;
            size_t orow = ((size_t)bb * S_ + nn + 1) * D_;
            #pragma unroll
            for (int nt = 0; nt < 8; nt++) {
                int col = n0 + warp_n + nt * 8 + tig * 2;
                float v0 = acc[mt][nt][i * 2 + 0] + conv_b[col]     + pos[(size_t)(nn + 1) * D_ + col];
                float v1 = acc[mt][nt][i * 2 + 1] + conv_b[col + 1] + pos[(size_t)(nn + 1) * D_ + col + 1];
                g_x[orow + col] = v0;
                g_x[orow + col + 1] = v1;
                __nv_bfloat16 h, l;
                split_bf16(v0, h, l); g_xhi[orow + col] = h;     g_xlo[orow + col] = l;
                split_bf16(v1, h, l); g_xhi[orow + col + 1] = h; g_xlo[orow + col + 1] = l;
            }
        }
    }
}

// ---------------- weight transpose + split ----------------------------------
__global__ void wsplit_kernel(const float* __restrict__ W,
                              __nv_bfloat16* __restrict__ Dhi, __nv_bfloat16* __restrict__ Dlo,
                              int K, int N)
{
    __shared__ float t[32][33];
    int n0 = blockIdx.x * 32, k0 = blockIdx.y * 32;
    int tx = threadIdx.x, ty = threadIdx.y;
    #pragma unroll
    for (int j = 0; j < 32; j += 8)
        t[ty + j][tx] = W[(size_t)(k0 + ty + j) * N + n0 + tx];
    __syncthreads();
    #pragma unroll
    for (int j = 0; j < 32; j += 8) {
        float v = t[tx][ty + j];
        __nv_bfloat16 h, l;
        split_bf16(v, h, l);
        Dhi[(size_t)(n0 + ty + j) * K + k0 + tx] = h;
        Dlo[(size_t)(n0 + ty + j) * K + k0 + tx] = l;
    }
}

__global__ void conv_wsplit_kernel(const float* __restrict__ cw) {
    int idx = blockIdx.x * 256 + threadIdx.x;
    if (idx >= 512 * 8192) return;
    int o = idx >> 13;
    int r = idx & 8191;
    int p = r >> 9, ii = r & 511;
    float v = cw[(((size_t)o << 9) | ii) * 16 + p];
    __nv_bfloat16 h, l;
    split_bf16(v, h, l);
    g_whi[WOFF_CONV + idx] = h;
    g_wlo[WOFF_CONV + idx] = l;
}

// ---------------- small kernels ----------------------------------------------
__device__ __forceinline__ float block_sum(float v, float* sh) {
    int lane = threadIdx.x & 31, w = threadIdx.x >> 5;
    int nw = blockDim.x >> 5;
    #pragma unroll
    for (int o = 16; o > 0; o >>= 1) v += __shfl_xor_sync(0xffffffffu, v, o);
    if (lane == 0) sh[w] = v;
    __syncthreads();
    float tot = 0.f;
    for (int i = 0; i < nw; i++) tot += sh[i];
    __syncthreads();
    return tot;
}

__global__ void cls_kernel(const float* __restrict__ cls, const float* __restrict__ pos) {
    int b = blockIdx.x, d = threadIdx.x;
    float v = cls[d] + pos[d];
    size_t off = (size_t)b * S_ * D_ + d;
    g_x[off] = v;
    __nv_bfloat16 h, l;
    split_bf16(v, h, l);
    g_xhi[off] = h;
    g_xlo[off] = l;
}

__global__ void len_kernel(const float* __restrict__ mask) {
    __shared__ float sh[8];
    int b = blockIdx.x;
    float s = 0.f;
    for (int i = threadIdx.x; i < L_; i += 256) s += mask[(size_t)b * L_ + i];
    s = block_sum(s, sh);
    if (threadIdx.x == 0) g_len[b] = ceilf((s + 1.0f) / (float)P_);
}

__global__ void rope_elu_kernel() {
    int idx = blockIdx.x * 256 + threadIdx.x;
    if (idx >= M_ * H_ * 32) return;
    int t = idx & 31;
    int h = (idx >> 5) & 7;
    int m = idx >> 8;
    int b = m / S_;
    int s = m - b * S_;
    size_t base = (size_t)m * D_ + h * DH_;
    float inv = expf(-(float)t * 0.28782313662425575f);
    float f = (float)s * inv;
    float c = cosf(f), sn = sinf(f);

    float q1 = g_q[base + t], q2 = g_q[base + t + 32];
    float qa = q1 * c - q2 * sn;
    float qb = q2 * c + q1 * sn;
    g_q[base + t]      = qa > 0.f ? qa + 1.f : expf(qa);
    g_q[base + t + 32] = qb > 0.f ? qb + 1.f : expf(qb);

    float lm = ((float)s < g_len[b]) ? 1.f : 0.f;
    float k1 = g_k[base + t], k2 = g_k[base + t + 32];
    float ka = k1 * c - k2 * sn;
    float kb = k2 * c + k1 * sn;
    g_k[base + t]      = (ka > 0.f ? ka + 1.f : expf(ka)) * lm;
    g_k[base + t + 32] = (kb > 0.f ? kb + 1.f : expf(kb)) * lm;
}

__global__ __launch_bounds__(256) void kv_kernel() {
    __shared__ float kfs[16][64];
    __shared__ float vs[16][64];
    int bh = blockIdx.x;
    int b = bh >> 3, h = bh & 7;
    int tid = threadIdx.x;
    int ty = tid >> 4, tx = tid & 15;
    float acc[4][4];
    #pragma unroll
    for (int i = 0; i < 4; i++)
        #pragma unroll
        for (int j = 0; j < 4; j++) acc[i][j] = 0.f;

    for (int s0 = 0; s0 < S_; s0 += 16) {
        #pragma unroll
        for (int p = 0; p < 4; p++) {
            int e = tid + p * 256;
            int sl = e >> 6, d = e & 63;
            int s = s0 + sl;
            float kvv = 0.f, vv = 0.f;
            if (s < S_) {
                size_t off = ((size_t)(b * S_ + s)) * D_ + h * DH_ + d;
                kvv = g_k[off];
                vv  = g_v[off];
            }
            kfs[sl][d] = kvv;
            vs[sl][d]  = vv;
        }
        __syncthreads();
        #pragma unroll
        for (int kk = 0; kk < 16; kk++) {
            float a[4], bb[4];
            #pragma unroll
            for (int i = 0; i < 4; i++) { a[i] = kfs[kk][ty * 4 + i]; bb[i] = vs[kk][tx * 4 + i]; }
            #pragma unroll
            for (int i = 0; i < 4; i++)
                #pragma unroll
                for (int j = 0; j < 4; j++) acc[i][j] += a[i] * bb[j];
        }
        __syncthreads();
    }
    #pragma unroll
    for (int i = 0; i < 4; i++)
        #pragma unroll
        for (int j = 0; j < 4; j++)
            g_kv[((size_t)bh * 64 + ty * 4 + i) * 64 + tx * 4 + j] = acc[i][j];
}

__global__ void ksum_kernel() {
    int bh = blockIdx.x;
    int b = bh >> 3, h = bh & 7;
    int d = threadIdx.x;
    float acc = 0.f;
    for (int s = 0; s < S_; s++)
        acc += g_k[((size_t)(b * S_ + s)) * D_ + h * DH_ + d];
    g_ksum[(size_t)bh * 64 + d] = acc;
}

__global__ __launch_bounds__(256) void attn_kernel() {
    __shared__ float qf[512];
    int m = blockIdx.x;
    int b = m / S_;
    int tid = threadIdx.x;
    qf[tid]       = g_q[(size_t)m * D_ + tid];
    qf[tid + 256] = g_q[(size_t)m * D_ + tid + 256];
    __syncthreads();
    int h = tid >> 5, lane = tid & 31;
    const float* ks  = g_ksum + (size_t)(b * 8 + h) * 64;
    const float* qh  = qf + h * 64;
    const float* kvp = g_kv + (size_t)(b * 8 + h) * 4096;
    float zd = 0.f;
    #pragma unroll
    for (int d = 0; d < 64; d++) zd += qh[d] * ks[d];
    float z = 1.f / (zd + 1e-6f);
    float a0 = 0.f, a1 = 0.f;
    #pragma unroll
    for (int d = 0; d < 64; d++) {
        float qv = qh[d];
        a0 += qv * kvp[d * 64 + lane];
        a1 += qv * kvp[d * 64 + lane + 32];
    }
    a0 *= z; a1 *= z;
    size_t o0 = (size_t)m * D_ + h * 64 + lane;
    __nv_bfloat16 hh, ll;
    split_bf16(a0, hh, ll); g_ahi[o0] = hh; g_alo[o0] = ll;
    split_bf16(a1, hh, ll); g_ahi[o0 + 32] = hh; g_alo[o0 + 32] = ll;
}

__global__ __launch_bounds__(256) void ln_kernel(
    float* __restrict__ x, const float* __restrict__ sc, const float* __restrict__ bi,
    __nv_bfloat16* __restrict__ ohi, __nv_bfloat16* __restrict__ olo)
{
    __shared__ float sh[8];
    int row = blockIdx.x;
    float* p = x + (size_t)row * D_;
    int tid = threadIdx.x;
    float v0 = p[tid], v1 = p[tid + 256];
    float mean = block_sum(v0 + v1, sh) * (1.f / 512.f);
    float d0 = v0 - mean, d1 = v1 - mean;
    float var = block_sum(d0 * d0 + d1 * d1, sh) * (1.f / 512.f);
    float rstd = rsqrtf(var + 1e-5f);
    float y0 = d0 * rstd * sc[tid] + bi[tid];
    float y1 = d1 * rstd * sc[tid + 256] + bi[tid + 256];
    p[tid] = y0;
    p[tid + 256] = y1;
    __nv_bfloat16 h, l;
    split_bf16(y0, h, l);
    ohi[(size_t)row * D_ + tid] = h;
    olo[(size_t)row * D_ + tid] = l;
    split_bf16(y1, h, l);
    ohi[(size_t)row * D_ + tid + 256] = h;
    olo[(size_t)row * D_ + tid + 256] = l;
}

__global__ __launch_bounds__(128) void final_kernel(
    const float* __restrict__ lnf_s, const float* __restrict__ lnf_b,
    const float* __restrict__ out_w, const float* __restrict__ out_b,
    float* __restrict__ out)
{
    __shared__ float sh[8];
    __shared__ float xn[512];
    int b = blockIdx.x;
    int tid = threadIdx.x;
    const float* p = g_x + (size_t)b * S_ * D_;
    float v[4];
    #pragma unroll
    for (int i = 0; i < 4; i++) v[i] = p[tid + i * 128];
    float mean = block_sum(v[0] + v[1] + v[2] + v[3], sh) * (1.f / 512.f);
    float sq = 0.f;
    #pragma unroll
    for (int i = 0; i < 4; i++) { float d = v[i] - mean; sq += d * d; }
    float var = block_sum(sq, sh) * (1.f / 512.f);
    float rstd = rsqrtf(var + 1e-5f);
    #pragma unroll
    for (int i = 0; i < 4; i++) {
        int d = tid + i * 128;
        xn[d] = (v[i] - mean) * rstd * lnf_s[d] + lnf_b[d];
    }
    __syncthreads();
    int w = tid >> 5, lane = tid & 31;
    float acc = 0.f;
    for (int d = lane; d < 512; d += 32) acc += xn[d] * out_w[d * NC_ + w];
    #pragma unroll
    for (int o = 16; o > 0; o >>= 1) acc += __shfl_xor_sync(0xffffffffu, acc, o);
    if (lane == 0) out[b * NC_ + w] = acc + out_b[w];
}

// ---------------- host driver -----------------------------------------------
extern "C" void kernel_launch(void* const* d_in, const int* in_sizes, int n_in,
                              void* d_out, int out_size)
{
    const int*   inputs = (const int*)  d_in[0];
    const float* mask   = (const float*)d_in[1];
    const float* emb    = (const float*)d_in[2];
    const float* conv_w = (const float*)d_in[3];
    const float* conv_b = (const float*)d_in[4];
    const float* pos    = (const float*)d_in[5];
    const float* cls    = (const float*)d_in[6];
    const float* Wq     = (const float*)d_in[7];
    const float* bq     = (const float*)d_in[8];
    const float* Wk     = (const float*)d_in[9];
    const float* bk     = (const float*)d_in[10];
    const float* Wv     = (const float*)d_in[11];
    const float* bv     = (const float*)d_in[12];
    const float* Wo     = (const float*)d_in[13];
    const float* bo     = (const float*)d_in[14];
    const float* ln1_s  = (const float*)d_in[15];
    const float* ln1_b  = (const float*)d_in[16];
    const float* ln2_s  = (const float*)d_in[17];
    const float* ln2_b  = (const float*)d_in[18];
    const float* W1     = (const float*)d_in[19];
    const float* b1     = (const float*)d_in[20];
    const float* W2     = (const float*)d_in[21];
    const float* b2     = (const float*)d_in[22];
    const float* lnf_s  = (const float*)d_in[23];
    const float* lnf_b  = (const float*)d_in[24];
    const float* out_w  = (const float*)d_in[25];
    const float* out_b  = (const float*)d_in[26];
    float* out = (float*)d_out;

    cudaFuncSetAttribute(gemm_mma, cudaFuncAttributeMaxDynamicSharedMemorySize, SMEM_MMA);
    cudaFuncSetAttribute(convgemm_mma, cudaFuncAttributeMaxDynamicSharedMemorySize, SMEM_MMA);

    float *px, *pq, *pk, *pv;
    __nv_bfloat16 *pxhi, *pxlo, *pahi, *palo, *pfhi, *pflo, *pwhi, *pwlo;
    cudaGetSymbolAddress((void**)&px,   g_x);
    cudaGetSymbolAddress((void**)&pq,   g_q);
    cudaGetSymbolAddress((void**)&pk,   g_k);
    cudaGetSymbolAddress((void**)&pv,   g_v);
    cudaGetSymbolAddress((void**)&pxhi, g_xhi);
    cudaGetSymbolAddress((void**)&pxlo, g_xlo);
    cudaGetSymbolAddress((void**)&pahi, g_ahi);
    cudaGetSymbolAddress((void**)&palo, g_alo);
    cudaGetSymbolAddress((void**)&pfhi, g_fhi);
    cudaGetSymbolAddress((void**)&pflo, g_flo);
    cudaGetSymbolAddress((void**)&pwhi, g_whi);
    cudaGetSymbolAddress((void**)&pwlo, g_wlo);

    // weight prep
    conv_wsplit_kernel<<<(512 * 8192 + 255) / 256, 256>>>(conv_w);
    dim3 wb(32, 8);
    for (int i = 0; i < NL_; i++) {
        size_t lb = WOFF_L(i);
        wsplit_kernel<<<dim3(16, 16), wb>>>(Wq + (size_t)i * 262144, pwhi + lb + WO_Q, pwlo + lb + WO_Q, 512, 512);
        wsplit_kernel<<<dim3(16, 16), wb>>>(Wk + (size_t)i * 262144, pwhi + lb + WO_K, pwlo + lb + WO_K, 512, 512);
        wsplit_kernel<<<dim3(16, 16), wb>>>(Wv + (size_t)i * 262144, pwhi + lb + WO_V, pwlo + lb + WO_V, 512, 512);
        wsplit_kernel<<<dim3(16, 16), wb>>>(Wo + (size_t)i * 262144, pwhi + lb + WO_O, pwlo + lb + WO_O, 512, 512);
        wsplit_kernel<<<dim3(64, 16), wb>>>(W1 + (size_t)i * 1048576, pwhi + lb + WO_W1, pwlo + lb + WO_W1, 512, 2048);
        wsplit_kernel<<<dim3(16, 64), wb>>>(W2 + (size_t)i * 1048576, pwhi + lb + WO_W2, pwlo + lb + WO_W2, 2048, 512);
    }

    cls_kernel<<<B_, D_>>>(cls, pos);
    convgemm_mma<<<dim3(2, 64), 256, SMEM_MMA>>>(inputs, emb, conv_b, pos);
    len_kernel<<<B_, 256>>>(mask);

    dim3 gD(2, 65);   // N=512 / 256, M tiles 65
    dim3 gF(8, 65);   // N=2048 / 256

    for (int i = 0; i < NL_; i++) {
        size_t lb = WOFF_L(i);
        gemm_mma<<<gD, 256, SMEM_MMA>>>(pxhi, pxlo, pwhi + lb + WO_Q, pwlo + lb + WO_Q,
                                        bq + i * D_, nullptr, pq, nullptr, nullptr, M_, D_, D_, 0);
        gemm_mma<<<gD, 256, SMEM_MMA>>>(pxhi, pxlo, pwhi + lb + WO_K, pwlo + lb + WO_K,
                                        bk + i * D_, nullptr, pk, nullptr, nullptr, M_, D_, D_, 0);
        gemm_mma<<<gD, 256, SMEM_MMA>>>(pxhi, pxlo, pwhi + lb + WO_V, pwlo + lb + WO_V,
                                        bv + i * D_, nullptr, pv, nullptr, nullptr, M_, D_, D_, 0);
        rope_elu_kernel<<<(M_ * H_ * 32 + 255) / 256, 256>>>();
        kv_kernel<<<B_ * H_, 256>>>();
        ksum_kernel<<<B_ * H_, 64>>>();
        attn_kernel<<<M_, 256>>>();
        gemm_mma<<<gD, 256, SMEM_MMA>>>(pahi, palo, pwhi + lb + WO_O, pwlo + lb + WO_O,
                                        bo + i * D_, px, px, nullptr, nullptr, M_, D_, D_, 0);
        ln_kernel<<<M_, 256>>>(px, ln1_s + i * D_, ln1_b + i * D_, pxhi, pxlo);
        gemm_mma<<<gF, 256, SMEM_MMA>>>(pxhi, pxlo, pwhi + lb + WO_W1, pwlo + lb + WO_W1,
                                        b1 + i * FF_, nullptr, nullptr, pfhi, pflo, M_, FF_, D_, 1);
        gemm_mma<<<gD, 256, SMEM_MMA>>>(pfhi, pflo, pwhi + lb + WO_W2, pwlo + lb + WO_W2,
                                        b2 + i * D_, px, px, nullptr, nullptr, M_, D_, FF_, 0);
        ln_kernel<<<M_, 256>>>(px, ln2_s + i * D_, ln2_b + i * D_, pxhi, pxlo);
    }

    final_kernel<<<B_, 128>>>(lnf_s, lnf_b, out_w, out_b, out);
}